// round 14
// baseline (speedup 1.0000x reference)
#include <cuda_runtime.h>

#define Bv 2
#define CINv 64
#define COUTv 64
#define Hv 192
#define Wv 192
#define Gv 2
#define KKv 9
#define CGv 32
#define HWv (Hv*Wv)
#define PXB 128      // pixels per block (M tile)
#define SSTR2 132    // Ssm row stride (128 px + pad)

// ---------------- scratch (__device__ globals; no runtime alloc) ----------------
__device__ float g_nhwc[Bv*Hv*Wv*CINv];        // input transposed to NHWC
__device__ float g_py  [Bv*Gv*KKv*HWv];
__device__ float g_px  [Bv*Gv*KKv*HWv];
__device__ float g_dm  [Bv*Gv*KKv*HWv];
__device__ float g_wt  [Gv*KKv*CGv*COUTv];     // main weight transposed [g][k][c][o]
__device__ float g_wk  [KKv*64*28];            // sem+m2 weights transposed [k][c][oc(28)]

// ---------------- f32x2 packed helpers ----------------
__device__ __forceinline__ unsigned long long pack2(float lo, float hi) {
    unsigned long long r;
    asm("mov.b64 %0, {%1, %2};" : "=l"(r) : "f"(lo), "f"(hi));
    return r;
}
__device__ __forceinline__ void ffma2(unsigned long long &d,
                                      unsigned long long a,
                                      unsigned long long b) {
    asm("fma.rn.f32x2 %0, %1, %2, %0;" : "+l"(d) : "l"(a), "l"(b));
}
__device__ __forceinline__ float2 unpack2(unsigned long long v) {
    float2 r;
    asm("mov.b64 {%0, %1}, %2;" : "=f"(r.x), "=f"(r.y) : "l"(v));
    return r;
}
__device__ __forceinline__ void nbar_sync(int id, int cnt) {
    asm volatile("bar.sync %0, %1;" :: "r"(id), "r"(cnt) : "memory");
}
__device__ __forceinline__ void nbar_arrive(int id, int cnt) {
    asm volatile("bar.arrive %0, %1;" :: "r"(id), "r"(cnt) : "memory");
}

// ---------------- kernel: NCHW -> NHWC transpose (smem tiled) ----------------
__global__ void k_transpose(const float* __restrict__ in) {
    __shared__ float tile[64][33];
    int b  = blockIdx.z;
    int h  = blockIdx.y;
    int w0 = blockIdx.x * 32;
    int tw = threadIdx.x & 31;
    int tc = threadIdx.x >> 5;
    #pragma unroll
    for (int c = tc; c < 64; c += 8)
        tile[c][tw] = in[(((size_t)b*CINv + c)*Hv + h)*Wv + w0 + tw];
    __syncthreads();
    int oc = threadIdx.x & 63;
    #pragma unroll
    for (int j = threadIdx.x >> 6; j < 32; j += 4)
        g_nhwc[(((size_t)b*Hv + h)*Wv + w0 + j)*CINv + oc] = tile[oc][j];
}

// ---------------- kernel: transpose weights ----------------
__global__ void k_prep(const float* __restrict__ weight,
                       const float* __restrict__ sem_w,
                       const float* __restrict__ m2_w) {
    int i = blockIdx.x * 256 + threadIdx.x;
    if (i < Gv*KKv*CGv*COUTv) {
        int o = i & 63;
        int c = (i >> 6) & 31;
        int k = (i >> 11) % KKv;
        int g = i / (2048 * KKv);
        g_wt[i] = weight[((size_t)o*CINv + g*CGv + c)*KKv + k];
    }
    if (i < KKv*64*28) {
        int oc = i % 28;
        int c  = (i / 28) % 64;
        int k  = i / (28 * 64);
        float v = 0.f;
        if (oc < 18)      v = sem_w[((size_t)oc*64 + c)*KKv + k];
        else if (oc < 27) v = m2_w[((size_t)(oc-18)*64 + c)*KKv + k];
        g_wk[i] = v;
    }
}

// ---------------- kernel: offsets + modulation masks + update_mask ----------------
__global__ void __launch_bounds__(128)
k_offsets(const float* __restrict__ input,
          const float* __restrict__ mask,
          const float* __restrict__ sem_b,
          const float* __restrict__ reg_w, const float* __restrict__ reg_b,
          const float* __restrict__ m1_w,  const float* __restrict__ m1_b,
          const float* __restrict__ m2_b,
          float* __restrict__ out) {
    extern __shared__ float wsm[];   // [k][c][28] = 16128 floats
    for (int i = threadIdx.x * 4; i < KKv*64*28; i += 128 * 4)
        *(float4*)(wsm + i) = *(const float4*)(g_wk + i);
    __syncthreads();

    int pix = blockIdx.x * 128 + threadIdx.x;
    int b  = pix / HWv;
    int hw = pix % HWv;
    int h  = hw / Wv;
    int w  = hw % Wv;

    unsigned long long acc[14];
    #pragma unroll
    for (int j = 0; j < 14; j++) {
        int a = 2*j, c2 = 2*j + 1;
        float lo = (a  < 18) ? sem_b[a]  : ((a  < 27) ? m2_b[a  - 18] : 0.f);
        float hi = (c2 < 18) ? sem_b[c2] : ((c2 < 27) ? m2_b[c2 - 18] : 0.f);
        acc[j] = pack2(lo, hi);
    }

    #pragma unroll 1
    for (int k = 0; k < 9; k++) {
        int yy = h + k / 3 - 1, xx = w + k % 3 - 1;
        if ((unsigned)yy < Hv && (unsigned)xx < Wv) {
            const float* xp = input + (size_t)b*CINv*HWv + yy*Wv + xx;
            const float* wrow = wsm + k * 64 * 28;
            #pragma unroll 4
            for (int c = 0; c < 64; c++) {
                float x = xp[c * HWv];
                unsigned long long s2 = pack2(x, x);
                const ulonglong2* wp = (const ulonglong2*)(wrow + c * 28);
                #pragma unroll
                for (int j2 = 0; j2 < 7; j2++) {
                    ulonglong2 q = wp[j2];
                    ffma2(acc[2*j2],     s2, q.x);
                    ffma2(acc[2*j2 + 1], s2, q.y);
                }
            }
        }
    }
    float res[28];
    #pragma unroll
    for (int j = 0; j < 14; j++) { float2 t = unpack2(acc[j]); res[2*j] = t.x; res[2*j+1] = t.y; }

    float mv[9];
    #pragma unroll
    for (int k = 0; k < 9; k++) {
        int yy = h + k / 3 - 1, xx = w + k % 3 - 1;
        mv[k] = ((unsigned)yy < Hv && (unsigned)xx < Wv) ? mask[(size_t)b*HWv + yy*Wv + xx] : 0.f;
    }
    float ro[18];
    #pragma unroll
    for (int i = 0; i < 18; i++) {
        float s = reg_b[i];
        #pragma unroll
        for (int k = 0; k < 9; k++) s += mv[k] * __ldg(&reg_w[i*9 + k]);
        ro[i] = s;
    }
    float d1[9];
    #pragma unroll
    for (int j = 0; j < 9; j++) {
        float s = m1_b[j];
        #pragma unroll
        for (int k = 0; k < 9; k++) s += mv[k] * __ldg(&m1_w[j*9 + k]);
        d1[j] = 1.f / (1.f + __expf(-s));
    }

    const float* mb = mask + (size_t)b * HWv;
    float umsum = 0.f;
    #pragma unroll
    for (int g = 0; g < 2; g++) {
        #pragma unroll
        for (int k = 0; k < 9; k++) {
            float dy = g ? res[2*k]     : ro[2*k];
            float dx = g ? res[2*k + 1] : ro[2*k + 1];
            float py = dy + (float)h + (float)(k / 3 - 1);
            float px = dx + (float)w + (float)(k % 3 - 1);
            int idx = (((b*2 + g)*9) + k) * HWv + hw;
            g_py[idx] = py;
            g_px[idx] = px;
            g_dm[idx] = g ? (1.f / (1.f + __expf(-res[18 + k]))) : d1[k];

            float y0f = floorf(py), x0f = floorf(px);
            int y0 = (int)y0f, x0 = (int)x0f;
            float ly = py - y0f, lx = px - x0f;
            float v00 = ((unsigned)y0     < Hv && (unsigned)x0     < Wv) ? mb[y0*Wv + x0]         : 0.f;
            float v01 = ((unsigned)y0     < Hv && (unsigned)(x0+1) < Wv) ? mb[y0*Wv + x0 + 1]     : 0.f;
            float v10 = ((unsigned)(y0+1) < Hv && (unsigned)x0     < Wv) ? mb[(y0+1)*Wv + x0]     : 0.f;
            float v11 = ((unsigned)(y0+1) < Hv && (unsigned)(x0+1) < Wv) ? mb[(y0+1)*Wv + x0 + 1] : 0.f;
            umsum += (v00*(1.f-ly) + v10*ly)*(1.f-lx) + (v01*(1.f-ly) + v11*ly)*lx;
        }
    }
    out[(size_t)Bv*COUTv*HWv + (size_t)b*HWv + hw] = fminf(fmaxf(64.f * umsum, 0.f), 1.f);
}

// ---------------- fused gather + GEMM: warp-spec, high-occupancy consumers ----------------
// block = 384 thr (12 warps): warps 0-7 consumers (4o x 8px each, 16 f32x2 acc),
// warps 8-11 producers (32 px each). 2 blocks/SM -> 24 warps (37.5% occ),
// 4 consumer warps per SMSP for latency coverage. Named barriers:
//   full[buf]  (id 1+buf): producers arrive, consumers sync   (count 384)
//   empty[buf] (id 3+buf): consumers arrive (kk<16), producers sync (kk>=2)
__global__ void __launch_bounds__(384, 2)
k_fused(const float* __restrict__ bias, float* __restrict__ out) {
    extern __shared__ float dsm[];
    float*  Wsm = dsm;                         // 2 x 2048
    float*  Ssm = dsm + 4096;                  // 2 x 32*SSTR2 = 8448
    int4*   po  = (int4*)(dsm + 4096 + 8448);  // 128 (single buffer, producer-local)
    float4* pw  = (float4*)(po + 128);         // 128

    int t   = threadIdx.x;
    int wid = t >> 5, l = t & 31;
    int b   = blockIdx.x / (HWv / PXB);
    int hw0 = (blockIdx.x % (HWv / PXB)) * PXB;

    if (wid < 8) {
        // ===================== CONSUMER (8 warps, 4o x 8px per thread) =====================
        int og = t >> 4;        // 0..15
        int pg = t & 15;        // 0..15
        int ob = og << 2;       // out-channel base (0,4,...,60)

        unsigned long long acc[16];
        #pragma unroll
        for (int j = 0; j < 16; j++) acc[j] = 0ull;

        #pragma unroll 1
        for (int kk = 0; kk < 18; kk++) {
            int buf = kk & 1;
            nbar_sync(1 + buf, 384);          // wait full
            const float* Sc = Ssm + buf*32*SSTR2;
            const float* Wc = Wsm + buf*2048;
            #pragma unroll 4
            for (int c = 0; c < 32; c++) {
                ulonglong2 s01 = *(const ulonglong2*)(Sc + c * SSTR2 + 4*pg);
                ulonglong2 s23 = *(const ulonglong2*)(Sc + c * SSTR2 + 64 + 4*pg);
                float4 w0 = *(const float4*)(Wc + c * 64 + ob);
                float wa[4] = {w0.x, w0.y, w0.z, w0.w};
                #pragma unroll
                for (int e = 0; e < 4; e++) {
                    unsigned long long w2 = pack2(wa[e], wa[e]);
                    ffma2(acc[e*4 + 0], w2, s01.x);
                    ffma2(acc[e*4 + 1], w2, s01.y);
                    ffma2(acc[e*4 + 2], w2, s23.x);
                    ffma2(acc[e*4 + 3], w2, s23.y);
                }
            }
            if (kk < 16) nbar_arrive(3 + buf, 384);   // signal empty (matched by prod kk+2)
        }

        // epilogue: (acc + bias) * update_mask
        const float* umB = out + (size_t)Bv*COUTv*HWv + (size_t)b*HWv + hw0;
        float4 um0 = *(const float4*)(umB + 4*pg);
        float4 um1 = *(const float4*)(umB + 64 + 4*pg);
        #pragma unroll
        for (int e = 0; e < 4; e++) {
            float bv = bias[ob + e];
            float2 r0 = unpack2(acc[e*4 + 0]);
            float2 r1 = unpack2(acc[e*4 + 1]);
            float2 r2 = unpack2(acc[e*4 + 2]);
            float2 r3 = unpack2(acc[e*4 + 3]);
            float* op = out + ((size_t)b*COUTv + ob + e)*HWv + hw0;
            float4 o0 = {(r0.x + bv)*um0.x, (r0.y + bv)*um0.y,
                         (r1.x + bv)*um0.z, (r1.y + bv)*um0.w};
            float4 o1 = {(r2.x + bv)*um1.x, (r2.y + bv)*um1.y,
                         (r3.x + bv)*um1.z, (r3.y + bv)*um1.w};
            *(float4*)(op + 4*pg)      = o0;
            *(float4*)(op + 64 + 4*pg) = o1;
        }
    } else {
        // ===================== PRODUCER (4 warps) =====================
        int p_   = wid - 8;                   // 0..3 -> pixels [32p_, 32p_+32)
        int base = t - 256;                   // 0..127
        const float* xb = g_nhwc + ((size_t)b * HWv) * 64 + l;

        #pragma unroll 1
        for (int kk = 0; kk < 18; kk++) {
            int buf = kk & 1;
            if (kk >= 2) nbar_sync(3 + buf, 384);     // wait empty

            // stage W slice (2048 floats over 128 threads = 4 float4 each)
            {
                const float4* wsrc = (const float4*)(g_wt + kk * 2048);
                float4* wdst = (float4*)(Wsm + buf*2048);
                #pragma unroll
                for (int i = 0; i < 4; i++) wdst[base + i*128] = wsrc[base + i*128];
            }
            // params: warp-local — lane l handles pixel 32p_+l
            {
                int p  = 32*p_ + l;
                int gi = (b * 18 + kk) * HWv + hw0 + p;
                float py = g_py[gi], px = g_px[gi], dm = g_dm[gi];
                float y0f = floorf(py), x0f = floorf(px);
                int y0 = (int)y0f, x0 = (int)x0f;
                float ly = py - y0f, lx = px - x0f;
                bool vy0 = (unsigned)y0       < Hv;
                bool vy1 = (unsigned)(y0 + 1) < Hv;
                bool vx0 = (unsigned)x0       < Wv;
                bool vx1 = (unsigned)(x0 + 1) < Wv;
                float w00 = (vy0 && vx0) ? (1.f-ly)*(1.f-lx)*dm : 0.f;
                float w01 = (vy0 && vx1) ? (1.f-ly)*lx*dm       : 0.f;
                float w10 = (vy1 && vx0) ? ly*(1.f-lx)*dm       : 0.f;
                float w11 = (vy1 && vx1) ? ly*lx*dm             : 0.f;
                int yc0 = min(max(y0, 0), Hv-1),   yc1 = min(max(y0+1, 0), Hv-1);
                int xc0 = min(max(x0, 0), Wv-1),   xc1 = min(max(x0+1, 0), Wv-1);
                po[p] = make_int4((yc0*Wv + xc0)*64, (yc0*Wv + xc1)*64,
                                  (yc1*Wv + xc0)*64, (yc1*Wv + xc1)*64);
                pw[p] = make_float4(w00, w01, w10, w11);
            }
            __syncwarp();

            // gather: lane = channel l, warp covers pixels [32p_, 32p_+32)
            const float* xg = xb + (kk / 9) * 32;
            float* srow = Ssm + buf*32*SSTR2 + l * SSTR2 + 32 * p_;
            #pragma unroll 4
            for (int j = 0; j < 8; j++) {
                float v[4];
                #pragma unroll
                for (int e = 0; e < 4; e++) {
                    int p = 32*p_ + 4*j + e;
                    int4   o  = po[p];
                    float4 wv = pw[p];
                    v[e] = xg[o.x]*wv.x + xg[o.y]*wv.y + xg[o.z]*wv.z + xg[o.w]*wv.w;
                }
                *(float4*)(srow + 4*j) = make_float4(v[0], v[1], v[2], v[3]);
            }
            __threadfence_block();
            nbar_arrive(1 + buf, 384);        // signal full
        }
    }
}

// ---------------- launcher ----------------
extern "C" void kernel_launch(void* const* d_in, const int* in_sizes, int n_in,
                              void* d_out, int out_size) {
    const float* input  = (const float*)d_in[0];
    const float* mask   = (const float*)d_in[1];
    const float* weight = (const float*)d_in[2];
    const float* bias   = (const float*)d_in[3];
    const float* sem_w  = (const float*)d_in[4];
    const float* sem_b  = (const float*)d_in[5];
    const float* reg_w  = (const float*)d_in[6];
    const float* reg_b  = (const float*)d_in[7];
    const float* m1_w   = (const float*)d_in[8];
    const float* m1_b   = (const float*)d_in[9];
    const float* m2_w   = (const float*)d_in[10];
    const float* m2_b   = (const float*)d_in[11];
    float* out = (float*)d_out;

    const int fusedSmem = (4096 + 2*32*SSTR2) * 4 + 128*16 + 128*16;  // 54272 B

    cudaFuncSetAttribute(k_offsets, cudaFuncAttributeMaxDynamicSharedMemorySize, KKv*64*28*4);
    cudaFuncSetAttribute(k_fused,   cudaFuncAttributeMaxDynamicSharedMemorySize, fusedSmem);

    k_transpose<<<dim3(Wv/32, Hv, Bv), 256>>>(input);
    k_prep<<<(Gv*KKv*CGv*COUTv + 255)/256, 256>>>(weight, sem_w, m2_w);
    k_offsets<<<(Bv*HWv)/128, 128, KKv*64*28*4>>>(input, mask, sem_b, reg_w, reg_b,
                                                  m1_w, m1_b, m2_b, out);
    k_fused<<<(Bv*HWv)/PXB, 384, fusedSmem>>>(bias, out);
}

// round 15
// speedup vs baseline: 1.3145x; 1.3145x over previous
#include <cuda_runtime.h>

#define Bv 2
#define CINv 64
#define COUTv 64
#define Hv 192
#define Wv 192
#define Gv 2
#define KKv 9
#define CGv 32
#define HWv (Hv*Wv)
#define PXB 128      // pixels per block (M tile) in k_fused
#define SSTR2 132    // Ssm row stride (128 px + pad)

// ---------------- scratch (__device__ globals; no runtime alloc) ----------------
__device__ float g_nhwc[Bv*Hv*Wv*CINv];        // input transposed to NHWC
__device__ float g_py  [Bv*Gv*KKv*HWv];
__device__ float g_px  [Bv*Gv*KKv*HWv];
__device__ float g_dm  [Bv*Gv*KKv*HWv];
__device__ float g_wt  [Gv*KKv*CGv*COUTv];     // main weight transposed [g][k][c][o]
__device__ float g_wk  [KKv*64*28];            // sem+m2 weights transposed [k][c][oc(28)]

// ---------------- f32x2 packed helpers ----------------
__device__ __forceinline__ unsigned long long pack2(float lo, float hi) {
    unsigned long long r;
    asm("mov.b64 %0, {%1, %2};" : "=l"(r) : "f"(lo), "f"(hi));
    return r;
}
__device__ __forceinline__ void ffma2(unsigned long long &d,
                                      unsigned long long a,
                                      unsigned long long b) {
    asm("fma.rn.f32x2 %0, %1, %2, %0;" : "+l"(d) : "l"(a), "l"(b));
}
__device__ __forceinline__ float2 unpack2(unsigned long long v) {
    float2 r;
    asm("mov.b64 {%0, %1}, %2;" : "=f"(r.x), "=f"(r.y) : "l"(v));
    return r;
}
__device__ __forceinline__ void nbar_sync(int id, int cnt) {
    asm volatile("bar.sync %0, %1;" :: "r"(id), "r"(cnt) : "memory");
}
__device__ __forceinline__ void nbar_arrive(int id, int cnt) {
    asm volatile("bar.arrive %0, %1;" :: "r"(id), "r"(cnt) : "memory");
}

// ---------------- kernel: NCHW -> NHWC transpose (smem tiled) ----------------
__global__ void k_transpose(const float* __restrict__ in) {
    __shared__ float tile[64][33];
    int b  = blockIdx.z;
    int h  = blockIdx.y;
    int w0 = blockIdx.x * 32;
    int tw = threadIdx.x & 31;
    int tc = threadIdx.x >> 5;
    #pragma unroll
    for (int c = tc; c < 64; c += 8)
        tile[c][tw] = in[(((size_t)b*CINv + c)*Hv + h)*Wv + w0 + tw];
    __syncthreads();
    int oc = threadIdx.x & 63;
    #pragma unroll
    for (int j = threadIdx.x >> 6; j < 32; j += 4)
        g_nhwc[(((size_t)b*Hv + h)*Wv + w0 + j)*CINv + oc] = tile[oc][j];
}

// ---------------- kernel: transpose weights ----------------
__global__ void k_prep(const float* __restrict__ weight,
                       const float* __restrict__ sem_w,
                       const float* __restrict__ m2_w) {
    int i = blockIdx.x * 256 + threadIdx.x;
    if (i < Gv*KKv*CGv*COUTv) {
        int o = i & 63;
        int c = (i >> 6) & 31;
        int k = (i >> 11) % KKv;
        int g = i / (2048 * KKv);
        g_wt[i] = weight[((size_t)o*CINv + g*CGv + c)*KKv + k];
    }
    if (i < KKv*64*28) {
        int oc = i % 28;
        int c  = (i / 28) % 64;
        int k  = i / (28 * 64);
        float v = 0.f;
        if (oc < 18)      v = sem_w[((size_t)oc*64 + c)*KKv + k];
        else if (oc < 27) v = m2_w[((size_t)(oc-18)*64 + c)*KKv + k];
        g_wk[i] = v;
    }
}

// ---------------- kernel: offsets + masks, 2 pixels per thread ----------------
// Thread t handles pixels hw0+t and hw0+128+t (both coalesced).
// acc[oc] packs (pixelA, pixelB); weights are scalar broadcasts shared by both
// pixels -> LDS-per-pixel halved vs the oc-packed version.
__global__ void __launch_bounds__(128)
k_offsets(const float* __restrict__ input,
          const float* __restrict__ mask,
          const float* __restrict__ sem_b,
          const float* __restrict__ reg_w, const float* __restrict__ reg_b,
          const float* __restrict__ m1_w,  const float* __restrict__ m1_b,
          const float* __restrict__ m2_b,
          float* __restrict__ out) {
    extern __shared__ float wsm[];   // [k][c][28] = 16128 floats
    for (int i = threadIdx.x * 4; i < KKv*64*28; i += 128 * 4)
        *(float4*)(wsm + i) = *(const float4*)(g_wk + i);
    __syncthreads();

    int pixA = blockIdx.x * 256 + threadIdx.x;       // pixel A
    int b   = pixA / HWv;                            // block spans one image (256 | HW)
    int hwA = pixA % HWv;
    int hwB = hwA + 128;
    int hA = hwA / Wv, wA = hwA % Wv;
    int hB = hwB / Wv, wB = hwB % Wv;

    unsigned long long acc[28];
    #pragma unroll
    for (int oc = 0; oc < 28; oc++) {
        float bv = (oc < 18) ? sem_b[oc] : ((oc < 27) ? m2_b[oc - 18] : 0.f);
        acc[oc] = pack2(bv, bv);
    }

    const float* xbase = input + (size_t)b*CINv*HWv;

    #pragma unroll 1
    for (int k = 0; k < 9; k++) {
        int dy = k / 3 - 1, dx = k % 3 - 1;
        int yA = hA + dy, xA = wA + dx;
        int yB = hB + dy, xB = wB + dx;
        bool vA = (unsigned)yA < Hv && (unsigned)xA < Wv;
        bool vB = (unsigned)yB < Hv && (unsigned)xB < Wv;
        const float* xpA = xbase + (vA ? (yA*Wv + xA) : 0);
        const float* xpB = xbase + (vB ? (yB*Wv + xB) : 0);
        const float* wrow = wsm + k * 64 * 28;
        #pragma unroll 4
        for (int c = 0; c < 64; c++) {
            float x0 = vA ? xpA[c * HWv] : 0.f;
            float x1 = vB ? xpB[c * HWv] : 0.f;
            unsigned long long s2 = pack2(x0, x1);
            const float4* wp = (const float4*)(wrow + c * 28);
            #pragma unroll
            for (int q = 0; q < 7; q++) {
                float4 wq = wp[q];
                ffma2(acc[q*4 + 0], s2, pack2(wq.x, wq.x));
                ffma2(acc[q*4 + 1], s2, pack2(wq.y, wq.y));
                ffma2(acc[q*4 + 2], s2, pack2(wq.z, wq.z));
                ffma2(acc[q*4 + 3], s2, pack2(wq.w, wq.w));
            }
        }
    }

    // per-pixel epilogue (reg/m1 convs from 1-ch mask, update_mask, stores)
    const float* mb = mask + (size_t)b * HWv;
    #pragma unroll 1
    for (int pp = 0; pp < 2; pp++) {
        int hw = pp ? hwB : hwA;
        int h  = pp ? hB  : hA;
        int w  = pp ? wB  : wA;
        float res[28];
        #pragma unroll
        for (int oc = 0; oc < 28; oc++) {
            float2 v = unpack2(acc[oc]);
            res[oc] = pp ? v.y : v.x;
        }

        float mv[9];
        #pragma unroll
        for (int k = 0; k < 9; k++) {
            int yy = h + k / 3 - 1, xx = w + k % 3 - 1;
            mv[k] = ((unsigned)yy < Hv && (unsigned)xx < Wv) ? mb[yy*Wv + xx] : 0.f;
        }
        float ro[18];
        #pragma unroll
        for (int i = 0; i < 18; i++) {
            float s = reg_b[i];
            #pragma unroll
            for (int k = 0; k < 9; k++) s += mv[k] * __ldg(&reg_w[i*9 + k]);
            ro[i] = s;
        }
        float d1[9];
        #pragma unroll
        for (int j = 0; j < 9; j++) {
            float s = m1_b[j];
            #pragma unroll
            for (int k = 0; k < 9; k++) s += mv[k] * __ldg(&m1_w[j*9 + k]);
            d1[j] = 1.f / (1.f + __expf(-s));
        }

        float umsum = 0.f;
        #pragma unroll
        for (int g = 0; g < 2; g++) {
            #pragma unroll
            for (int k = 0; k < 9; k++) {
                float dyv = g ? res[2*k]     : ro[2*k];
                float dxv = g ? res[2*k + 1] : ro[2*k + 1];
                float py = dyv + (float)h + (float)(k / 3 - 1);
                float px = dxv + (float)w + (float)(k % 3 - 1);
                int idx = (((b*2 + g)*9) + k) * HWv + hw;
                g_py[idx] = py;
                g_px[idx] = px;
                g_dm[idx] = g ? (1.f / (1.f + __expf(-res[18 + k]))) : d1[k];

                float y0f = floorf(py), x0f = floorf(px);
                int y0 = (int)y0f, x0 = (int)x0f;
                float ly = py - y0f, lx = px - x0f;
                float v00 = ((unsigned)y0     < Hv && (unsigned)x0     < Wv) ? mb[y0*Wv + x0]         : 0.f;
                float v01 = ((unsigned)y0     < Hv && (unsigned)(x0+1) < Wv) ? mb[y0*Wv + x0 + 1]     : 0.f;
                float v10 = ((unsigned)(y0+1) < Hv && (unsigned)x0     < Wv) ? mb[(y0+1)*Wv + x0]     : 0.f;
                float v11 = ((unsigned)(y0+1) < Hv && (unsigned)(x0+1) < Wv) ? mb[(y0+1)*Wv + x0 + 1] : 0.f;
                umsum += (v00*(1.f-ly) + v10*ly)*(1.f-lx) + (v01*(1.f-ly) + v11*ly)*lx;
            }
        }
        out[(size_t)Bv*COUTv*HWv + (size_t)b*HWv + hw] = fminf(fmaxf(64.f * umsum, 0.f), 1.f);
    }
}

// ---------------- fused gather + GEMM: balanced warp specialization (R13) ----------------
__global__ void __launch_bounds__(256, 2)
k_fused(const float* __restrict__ bias, float* __restrict__ out) {
    extern __shared__ float dsm[];
    float*  Wsm = dsm;                         // 2 x 2048
    float*  Ssm = dsm + 4096;                  // 2 x 32*SSTR2 = 8448
    int4*   po  = (int4*)(dsm + 4096 + 8448);  // 128
    float4* pw  = (float4*)(po + 128);         // 128

    int t   = threadIdx.x;
    int wid = t >> 5, l = t & 31;
    int b   = blockIdx.x / (HWv / PXB);
    int hw0 = (blockIdx.x % (HWv / PXB)) * PXB;

    if (wid < 4) {
        // ===================== CONSUMER =====================
        int og = t >> 4;
        int pg = t & 15;
        int ob = og << 3;

        unsigned long long acc[32];
        #pragma unroll
        for (int j = 0; j < 32; j++) acc[j] = 0ull;

        #pragma unroll 1
        for (int kk = 0; kk < 18; kk++) {
            int buf = kk & 1;
            nbar_sync(1 + buf, 256);
            const float* Sc = Ssm + buf*32*SSTR2;
            const float* Wc = Wsm + buf*2048;
            #pragma unroll 2
            for (int c = 0; c < 32; c++) {
                ulonglong2 s01 = *(const ulonglong2*)(Sc + c * SSTR2 + 4*pg);
                ulonglong2 s23 = *(const ulonglong2*)(Sc + c * SSTR2 + 64 + 4*pg);
                float4 w0 = *(const float4*)(Wc + c * 64 + ob);
                float4 w1 = *(const float4*)(Wc + c * 64 + ob + 4);
                float wa[8] = {w0.x, w0.y, w0.z, w0.w, w1.x, w1.y, w1.z, w1.w};
                #pragma unroll
                for (int e = 0; e < 8; e++) {
                    unsigned long long w2 = pack2(wa[e], wa[e]);
                    ffma2(acc[e*4 + 0], w2, s01.x);
                    ffma2(acc[e*4 + 1], w2, s01.y);
                    ffma2(acc[e*4 + 2], w2, s23.x);
                    ffma2(acc[e*4 + 3], w2, s23.y);
                }
            }
            if (kk < 16) nbar_arrive(3 + buf, 256);
        }

        const float* umB = out + (size_t)Bv*COUTv*HWv + (size_t)b*HWv + hw0;
        float4 um0 = *(const float4*)(umB + 4*pg);
        float4 um1 = *(const float4*)(umB + 64 + 4*pg);
        #pragma unroll
        for (int e = 0; e < 8; e++) {
            float bv = bias[ob + e];
            float2 r0 = unpack2(acc[e*4 + 0]);
            float2 r1 = unpack2(acc[e*4 + 1]);
            float2 r2 = unpack2(acc[e*4 + 2]);
            float2 r3 = unpack2(acc[e*4 + 3]);
            float* op = out + ((size_t)b*COUTv + ob + e)*HWv + hw0;
            float4 o0 = {(r0.x + bv)*um0.x, (r0.y + bv)*um0.y,
                         (r1.x + bv)*um0.z, (r1.y + bv)*um0.w};
            float4 o1 = {(r2.x + bv)*um1.x, (r2.y + bv)*um1.y,
                         (r3.x + bv)*um1.z, (r3.y + bv)*um1.w};
            *(float4*)(op + 4*pg)      = o0;
            *(float4*)(op + 64 + 4*pg) = o1;
        }
    } else {
        // ===================== PRODUCER =====================
        int p_   = wid - 4;
        int base = t - 128;
        const float* xb = g_nhwc + ((size_t)b * HWv) * 64 + l;

        #pragma unroll 1
        for (int kk = 0; kk < 18; kk++) {
            int buf = kk & 1;
            if (kk >= 2) nbar_sync(3 + buf, 256);

            {
                const float4* wsrc = (const float4*)(g_wt + kk * 2048);
                float4* wdst = (float4*)(Wsm + buf*2048);
                #pragma unroll
                for (int i = 0; i < 4; i++) wdst[base + i*128] = wsrc[base + i*128];
            }
            {
                int p  = 32*p_ + l;
                int gi = (b * 18 + kk) * HWv + hw0 + p;
                float py = g_py[gi], px = g_px[gi], dm = g_dm[gi];
                float y0f = floorf(py), x0f = floorf(px);
                int y0 = (int)y0f, x0 = (int)x0f;
                float ly = py - y0f, lx = px - x0f;
                bool vy0 = (unsigned)y0       < Hv;
                bool vy1 = (unsigned)(y0 + 1) < Hv;
                bool vx0 = (unsigned)x0       < Wv;
                bool vx1 = (unsigned)(x0 + 1) < Wv;
                float w00 = (vy0 && vx0) ? (1.f-ly)*(1.f-lx)*dm : 0.f;
                float w01 = (vy0 && vx1) ? (1.f-ly)*lx*dm       : 0.f;
                float w10 = (vy1 && vx0) ? ly*(1.f-lx)*dm       : 0.f;
                float w11 = (vy1 && vx1) ? ly*lx*dm             : 0.f;
                int yc0 = min(max(y0, 0), Hv-1),   yc1 = min(max(y0+1, 0), Hv-1);
                int xc0 = min(max(x0, 0), Wv-1),   xc1 = min(max(x0+1, 0), Wv-1);
                po[p] = make_int4((yc0*Wv + xc0)*64, (yc0*Wv + xc1)*64,
                                  (yc1*Wv + xc0)*64, (yc1*Wv + xc1)*64);
                pw[p] = make_float4(w00, w01, w10, w11);
            }
            __syncwarp();

            const float* xg = xb + (kk / 9) * 32;
            float* srow = Ssm + buf*32*SSTR2 + l * SSTR2 + 32 * p_;
            #pragma unroll 4
            for (int j = 0; j < 8; j++) {
                float v[4];
                #pragma unroll
                for (int e = 0; e < 4; e++) {
                    int p = 32*p_ + 4*j + e;
                    int4   o  = po[p];
                    float4 wv = pw[p];
                    v[e] = xg[o.x]*wv.x + xg[o.y]*wv.y + xg[o.z]*wv.z + xg[o.w]*wv.w;
                }
                *(float4*)(srow + 4*j) = make_float4(v[0], v[1], v[2], v[3]);
            }
            __threadfence_block();
            nbar_arrive(1 + buf, 256);
        }
    }
}

// ---------------- launcher ----------------
extern "C" void kernel_launch(void* const* d_in, const int* in_sizes, int n_in,
                              void* d_out, int out_size) {
    const float* input  = (const float*)d_in[0];
    const float* mask   = (const float*)d_in[1];
    const float* weight = (const float*)d_in[2];
    const float* bias   = (const float*)d_in[3];
    const float* sem_w  = (const float*)d_in[4];
    const float* sem_b  = (const float*)d_in[5];
    const float* reg_w  = (const float*)d_in[6];
    const float* reg_b  = (const float*)d_in[7];
    const float* m1_w   = (const float*)d_in[8];
    const float* m1_b   = (const float*)d_in[9];
    const float* m2_w   = (const float*)d_in[10];
    const float* m2_b   = (const float*)d_in[11];
    float* out = (float*)d_out;

    const int fusedSmem = (4096 + 2*32*SSTR2) * 4 + 128*16 + 128*16;  // 54272 B

    cudaFuncSetAttribute(k_offsets, cudaFuncAttributeMaxDynamicSharedMemorySize, KKv*64*28*4);
    cudaFuncSetAttribute(k_fused,   cudaFuncAttributeMaxDynamicSharedMemorySize, fusedSmem);

    k_transpose<<<dim3(Wv/32, Hv, Bv), 256>>>(input);
    k_prep<<<(Gv*KKv*CGv*COUTv + 255)/256, 256>>>(weight, sem_w, m2_w);
    k_offsets<<<(Bv*HWv)/256, 128, KKv*64*28*4>>>(input, mask, sem_b, reg_w, reg_b,
                                                  m1_w, m1_b, m2_b, out);
    k_fused<<<(Bv*HWv)/PXB, 256, fusedSmem>>>(bias, out);
}

// round 16
// speedup vs baseline: 1.3555x; 1.0312x over previous
#include <cuda_runtime.h>

#define Bv 2
#define CINv 64
#define COUTv 64
#define Hv 192
#define Wv 192
#define Gv 2
#define KKv 9
#define CGv 32
#define HWv (Hv*Wv)
#define PXB 256      // pixels per block (M tile) in k_fused
#define SSTR3 264    // Ssm row stride (256 px + pad)

// ---------------- scratch (__device__ globals; no runtime alloc) ----------------
__device__ float g_nhwc[Bv*Hv*Wv*CINv];        // input transposed to NHWC
__device__ float g_py  [Bv*Gv*KKv*HWv];
__device__ float g_px  [Bv*Gv*KKv*HWv];
__device__ float g_dm  [Bv*Gv*KKv*HWv];
__device__ float g_wt  [Gv*KKv*CGv*COUTv];     // main weight transposed [g][k][c][o]
__device__ float g_wk  [KKv*64*28];            // sem+m2 weights transposed [k][c][oc(28)]

// ---------------- f32x2 packed helpers ----------------
__device__ __forceinline__ unsigned long long pack2(float lo, float hi) {
    unsigned long long r;
    asm("mov.b64 %0, {%1, %2};" : "=l"(r) : "f"(lo), "f"(hi));
    return r;
}
__device__ __forceinline__ void ffma2(unsigned long long &d,
                                      unsigned long long a,
                                      unsigned long long b) {
    asm("fma.rn.f32x2 %0, %1, %2, %0;" : "+l"(d) : "l"(a), "l"(b));
}
__device__ __forceinline__ float2 unpack2(unsigned long long v) {
    float2 r;
    asm("mov.b64 {%0, %1}, %2;" : "=f"(r.x), "=f"(r.y) : "l"(v));
    return r;
}
__device__ __forceinline__ void nbar_sync(int id, int cnt) {
    asm volatile("bar.sync %0, %1;" :: "r"(id), "r"(cnt) : "memory");
}
__device__ __forceinline__ void nbar_arrive(int id, int cnt) {
    asm volatile("bar.arrive %0, %1;" :: "r"(id), "r"(cnt) : "memory");
}

// ---------------- kernel: NCHW -> NHWC transpose (smem tiled) ----------------
__global__ void k_transpose(const float* __restrict__ in) {
    __shared__ float tile[64][33];
    int b  = blockIdx.z;
    int h  = blockIdx.y;
    int w0 = blockIdx.x * 32;
    int tw = threadIdx.x & 31;
    int tc = threadIdx.x >> 5;
    #pragma unroll
    for (int c = tc; c < 64; c += 8)
        tile[c][tw] = in[(((size_t)b*CINv + c)*Hv + h)*Wv + w0 + tw];
    __syncthreads();
    int oc = threadIdx.x & 63;
    #pragma unroll
    for (int j = threadIdx.x >> 6; j < 32; j += 4)
        g_nhwc[(((size_t)b*Hv + h)*Wv + w0 + j)*CINv + oc] = tile[oc][j];
}

// ---------------- kernel: transpose weights ----------------
__global__ void k_prep(const float* __restrict__ weight,
                       const float* __restrict__ sem_w,
                       const float* __restrict__ m2_w) {
    int i = blockIdx.x * 256 + threadIdx.x;
    if (i < Gv*KKv*CGv*COUTv) {
        int o = i & 63;
        int c = (i >> 6) & 31;
        int k = (i >> 11) % KKv;
        int g = i / (2048 * KKv);
        g_wt[i] = weight[((size_t)o*CINv + g*CGv + c)*KKv + k];
    }
    if (i < KKv*64*28) {
        int oc = i % 28;
        int c  = (i / 28) % 64;
        int k  = i / (28 * 64);
        float v = 0.f;
        if (oc < 18)      v = sem_w[((size_t)oc*64 + c)*KKv + k];
        else if (oc < 27) v = m2_w[((size_t)(oc-18)*64 + c)*KKv + k];
        g_wk[i] = v;
    }
}

// ---------------- kernel: offsets + masks, 2 pixels per thread (R15 WIN) ----------------
__global__ void __launch_bounds__(128)
k_offsets(const float* __restrict__ input,
          const float* __restrict__ mask,
          const float* __restrict__ sem_b,
          const float* __restrict__ reg_w, const float* __restrict__ reg_b,
          const float* __restrict__ m1_w,  const float* __restrict__ m1_b,
          const float* __restrict__ m2_b,
          float* __restrict__ out) {
    extern __shared__ float wsm[];   // [k][c][28] = 16128 floats
    for (int i = threadIdx.x * 4; i < KKv*64*28; i += 128 * 4)
        *(float4*)(wsm + i) = *(const float4*)(g_wk + i);
    __syncthreads();

    int pixA = blockIdx.x * 256 + threadIdx.x;
    int b   = pixA / HWv;
    int hwA = pixA % HWv;
    int hwB = hwA + 128;
    int hA = hwA / Wv, wA = hwA % Wv;
    int hB = hwB / Wv, wB = hwB % Wv;

    unsigned long long acc[28];
    #pragma unroll
    for (int oc = 0; oc < 28; oc++) {
        float bv = (oc < 18) ? sem_b[oc] : ((oc < 27) ? m2_b[oc - 18] : 0.f);
        acc[oc] = pack2(bv, bv);
    }

    const float* xbase = input + (size_t)b*CINv*HWv;

    #pragma unroll 1
    for (int k = 0; k < 9; k++) {
        int dy = k / 3 - 1, dx = k % 3 - 1;
        int yA = hA + dy, xA = wA + dx;
        int yB = hB + dy, xB = wB + dx;
        bool vA = (unsigned)yA < Hv && (unsigned)xA < Wv;
        bool vB = (unsigned)yB < Hv && (unsigned)xB < Wv;
        const float* xpA = xbase + (vA ? (yA*Wv + xA) : 0);
        const float* xpB = xbase + (vB ? (yB*Wv + xB) : 0);
        const float* wrow = wsm + k * 64 * 28;
        #pragma unroll 4
        for (int c = 0; c < 64; c++) {
            float x0 = vA ? xpA[c * HWv] : 0.f;
            float x1 = vB ? xpB[c * HWv] : 0.f;
            unsigned long long s2 = pack2(x0, x1);
            const float4* wp = (const float4*)(wrow + c * 28);
            #pragma unroll
            for (int q = 0; q < 7; q++) {
                float4 wq = wp[q];
                ffma2(acc[q*4 + 0], s2, pack2(wq.x, wq.x));
                ffma2(acc[q*4 + 1], s2, pack2(wq.y, wq.y));
                ffma2(acc[q*4 + 2], s2, pack2(wq.z, wq.z));
                ffma2(acc[q*4 + 3], s2, pack2(wq.w, wq.w));
            }
        }
    }

    const float* mb = mask + (size_t)b * HWv;
    #pragma unroll 1
    for (int pp = 0; pp < 2; pp++) {
        int hw = pp ? hwB : hwA;
        int h  = pp ? hB  : hA;
        int w  = pp ? wB  : wA;
        float res[28];
        #pragma unroll
        for (int oc = 0; oc < 28; oc++) {
            float2 v = unpack2(acc[oc]);
            res[oc] = pp ? v.y : v.x;
        }

        float mv[9];
        #pragma unroll
        for (int k = 0; k < 9; k++) {
            int yy = h + k / 3 - 1, xx = w + k % 3 - 1;
            mv[k] = ((unsigned)yy < Hv && (unsigned)xx < Wv) ? mb[yy*Wv + xx] : 0.f;
        }
        float ro[18];
        #pragma unroll
        for (int i = 0; i < 18; i++) {
            float s = reg_b[i];
            #pragma unroll
            for (int k = 0; k < 9; k++) s += mv[k] * __ldg(&reg_w[i*9 + k]);
            ro[i] = s;
        }
        float d1[9];
        #pragma unroll
        for (int j = 0; j < 9; j++) {
            float s = m1_b[j];
            #pragma unroll
            for (int k = 0; k < 9; k++) s += mv[k] * __ldg(&m1_w[j*9 + k]);
            d1[j] = 1.f / (1.f + __expf(-s));
        }

        float umsum = 0.f;
        #pragma unroll
        for (int g = 0; g < 2; g++) {
            #pragma unroll
            for (int k = 0; k < 9; k++) {
                float dyv = g ? res[2*k]     : ro[2*k];
                float dxv = g ? res[2*k + 1] : ro[2*k + 1];
                float py = dyv + (float)h + (float)(k / 3 - 1);
                float px = dxv + (float)w + (float)(k % 3 - 1);
                int idx = (((b*2 + g)*9) + k) * HWv + hw;
                g_py[idx] = py;
                g_px[idx] = px;
                g_dm[idx] = g ? (1.f / (1.f + __expf(-res[18 + k]))) : d1[k];

                float y0f = floorf(py), x0f = floorf(px);
                int y0 = (int)y0f, x0 = (int)x0f;
                float ly = py - y0f, lx = px - x0f;
                float v00 = ((unsigned)y0     < Hv && (unsigned)x0     < Wv) ? mb[y0*Wv + x0]         : 0.f;
                float v01 = ((unsigned)y0     < Hv && (unsigned)(x0+1) < Wv) ? mb[y0*Wv + x0 + 1]     : 0.f;
                float v10 = ((unsigned)(y0+1) < Hv && (unsigned)x0     < Wv) ? mb[(y0+1)*Wv + x0]     : 0.f;
                float v11 = ((unsigned)(y0+1) < Hv && (unsigned)(x0+1) < Wv) ? mb[(y0+1)*Wv + x0 + 1] : 0.f;
                umsum += (v00*(1.f-ly) + v10*ly)*(1.f-lx) + (v01*(1.f-ly) + v11*ly)*lx;
            }
        }
        out[(size_t)Bv*COUTv*HWv + (size_t)b*HWv + hw] = fminf(fmaxf(64.f * umsum, 0.f), 1.f);
    }
}

// ---------------- fused gather + GEMM: warp-spec, 512 thr, 1 block/SM ----------------
// 8 consumer warps (64o x 256px, 8o x 8px/thread) + 8 producer warps (32 px each).
// 1 block/SM -> 4 consumer warps per SMSP (2x latency coverage vs R13), no
// cross-block barrier interference. Double-buffered Ssm/Wsm; named barriers:
//   full[buf]  (id 1+buf): producers arrive, consumers sync  (count 512)
//   empty[buf] (id 3+buf): consumers arrive (kk<16), producers sync (kk>=2)
__global__ void __launch_bounds__(512, 1)
k_fused(const float* __restrict__ bias, float* __restrict__ out) {
    extern __shared__ float dsm[];
    float*  Wsm = dsm;                            // 2 x 2048
    float*  Ssm = dsm + 4096;                     // 2 x 32*SSTR3 = 16896
    int4*   po  = (int4*)(dsm + 4096 + 2*32*SSTR3);  // 256
    float4* pw  = (float4*)(po + 256);               // 256

    int t   = threadIdx.x;
    int wid = t >> 5, l = t & 31;
    int b   = blockIdx.x / (HWv / PXB);
    int hw0 = (blockIdx.x % (HWv / PXB)) * PXB;

    if (wid < 8) {
        // ===================== CONSUMER (8 warps) =====================
        int ob = wid << 3;      // warp-uniform out-channel base (0..56)
        int pg = l;             // pixel chunk selector 0..31

        unsigned long long acc[32];
        #pragma unroll
        for (int j = 0; j < 32; j++) acc[j] = 0ull;

        #pragma unroll 1
        for (int kk = 0; kk < 18; kk++) {
            int buf = kk & 1;
            nbar_sync(1 + buf, 512);          // wait full
            const float* Sc = Ssm + buf*32*SSTR3;
            const float* Wc = Wsm + buf*2048;
            #pragma unroll 2
            for (int c = 0; c < 32; c++) {
                ulonglong2 s01 = *(const ulonglong2*)(Sc + c * SSTR3 + 4*pg);
                ulonglong2 s23 = *(const ulonglong2*)(Sc + c * SSTR3 + 128 + 4*pg);
                float4 w0 = *(const float4*)(Wc + c * 64 + ob);
                float4 w1 = *(const float4*)(Wc + c * 64 + ob + 4);
                float wa[8] = {w0.x, w0.y, w0.z, w0.w, w1.x, w1.y, w1.z, w1.w};
                #pragma unroll
                for (int e = 0; e < 8; e++) {
                    unsigned long long w2 = pack2(wa[e], wa[e]);
                    ffma2(acc[e*4 + 0], w2, s01.x);
                    ffma2(acc[e*4 + 1], w2, s01.y);
                    ffma2(acc[e*4 + 2], w2, s23.x);
                    ffma2(acc[e*4 + 3], w2, s23.y);
                }
            }
            if (kk < 16) nbar_arrive(3 + buf, 512);   // signal empty
        }

        // epilogue: (acc + bias) * update_mask
        const float* umB = out + (size_t)Bv*COUTv*HWv + (size_t)b*HWv + hw0;
        float4 um0 = *(const float4*)(umB + 4*pg);
        float4 um1 = *(const float4*)(umB + 128 + 4*pg);
        #pragma unroll
        for (int e = 0; e < 8; e++) {
            float bv = bias[ob + e];
            float2 r0 = unpack2(acc[e*4 + 0]);
            float2 r1 = unpack2(acc[e*4 + 1]);
            float2 r2 = unpack2(acc[e*4 + 2]);
            float2 r3 = unpack2(acc[e*4 + 3]);
            float* op = out + ((size_t)b*COUTv + ob + e)*HWv + hw0;
            float4 o0 = {(r0.x + bv)*um0.x, (r0.y + bv)*um0.y,
                         (r1.x + bv)*um0.z, (r1.y + bv)*um0.w};
            float4 o1 = {(r2.x + bv)*um1.x, (r2.y + bv)*um1.y,
                         (r3.x + bv)*um1.z, (r3.y + bv)*um1.w};
            *(float4*)(op + 4*pg)       = o0;
            *(float4*)(op + 128 + 4*pg) = o1;
        }
    } else {
        // ===================== PRODUCER (8 warps, 32 px each) =====================
        int p_   = wid - 8;                   // 0..7 -> pixels [32p_, 32p_+32)
        int base = t - 256;                   // 0..255
        const float* xb = g_nhwc + ((size_t)b * HWv) * 64 + l;

        #pragma unroll 1
        for (int kk = 0; kk < 18; kk++) {
            int buf = kk & 1;
            if (kk >= 2) nbar_sync(3 + buf, 512);     // wait empty

            // stage W slice (2048 floats over 256 threads = 2 float4 each)
            {
                const float4* wsrc = (const float4*)(g_wt + kk * 2048);
                float4* wdst = (float4*)(Wsm + buf*2048);
                wdst[base]       = wsrc[base];
                wdst[base + 256] = wsrc[base + 256];
            }
            // params: warp-local — lane l handles pixel 32p_+l
            {
                int p  = 32*p_ + l;
                int gi = (b * 18 + kk) * HWv + hw0 + p;
                float py = g_py[gi], px = g_px[gi], dm = g_dm[gi];
                float y0f = floorf(py), x0f = floorf(px);
                int y0 = (int)y0f, x0 = (int)x0f;
                float ly = py - y0f, lx = px - x0f;
                bool vy0 = (unsigned)y0       < Hv;
                bool vy1 = (unsigned)(y0 + 1) < Hv;
                bool vx0 = (unsigned)x0       < Wv;
                bool vx1 = (unsigned)(x0 + 1) < Wv;
                float w00 = (vy0 && vx0) ? (1.f-ly)*(1.f-lx)*dm : 0.f;
                float w01 = (vy0 && vx1) ? (1.f-ly)*lx*dm       : 0.f;
                float w10 = (vy1 && vx0) ? ly*(1.f-lx)*dm       : 0.f;
                float w11 = (vy1 && vx1) ? ly*lx*dm             : 0.f;
                int yc0 = min(max(y0, 0), Hv-1),   yc1 = min(max(y0+1, 0), Hv-1);
                int xc0 = min(max(x0, 0), Wv-1),   xc1 = min(max(x0+1, 0), Wv-1);
                po[p] = make_int4((yc0*Wv + xc0)*64, (yc0*Wv + xc1)*64,
                                  (yc1*Wv + xc0)*64, (yc1*Wv + xc1)*64);
                pw[p] = make_float4(w00, w01, w10, w11);
            }
            __syncwarp();

            // gather: lane = channel l, warp covers pixels [32p_, 32p_+32)
            const float* xg = xb + (kk / 9) * 32;
            float* srow = Ssm + buf*32*SSTR3 + l * SSTR3 + 32 * p_;
            #pragma unroll 4
            for (int j = 0; j < 8; j++) {
                float v[4];
                #pragma unroll
                for (int e = 0; e < 4; e++) {
                    int p = 32*p_ + 4*j + e;
                    int4   o  = po[p];
                    float4 wv = pw[p];
                    v[e] = xg[o.x]*wv.x + xg[o.y]*wv.y + xg[o.z]*wv.z + xg[o.w]*wv.w;
                }
                *(float4*)(srow + 4*j) = make_float4(v[0], v[1], v[2], v[3]);
            }
            __threadfence_block();
            nbar_arrive(1 + buf, 512);        // signal full
        }
    }
}

// ---------------- launcher ----------------
extern "C" void kernel_launch(void* const* d_in, const int* in_sizes, int n_in,
                              void* d_out, int out_size) {
    const float* input  = (const float*)d_in[0];
    const float* mask   = (const float*)d_in[1];
    const float* weight = (const float*)d_in[2];
    const float* bias   = (const float*)d_in[3];
    const float* sem_w  = (const float*)d_in[4];
    const float* sem_b  = (const float*)d_in[5];
    const float* reg_w  = (const float*)d_in[6];
    const float* reg_b  = (const float*)d_in[7];
    const float* m1_w   = (const float*)d_in[8];
    const float* m1_b   = (const float*)d_in[9];
    const float* m2_w   = (const float*)d_in[10];
    const float* m2_b   = (const float*)d_in[11];
    float* out = (float*)d_out;

    const int fusedSmem = (4096 + 2*32*SSTR3) * 4 + 256*16 + 256*16;  // ~92KB

    cudaFuncSetAttribute(k_offsets, cudaFuncAttributeMaxDynamicSharedMemorySize, KKv*64*28*4);
    cudaFuncSetAttribute(k_fused,   cudaFuncAttributeMaxDynamicSharedMemorySize, fusedSmem);

    k_transpose<<<dim3(Wv/32, Hv, Bv), 256>>>(input);
    k_prep<<<(Gv*KKv*CGv*COUTv + 255)/256, 256>>>(weight, sem_w, m2_w);
    k_offsets<<<(Bv*HWv)/256, 128, KKv*64*28*4>>>(input, mask, sem_b, reg_w, reg_b,
                                                  m1_w, m1_b, m2_b, out);
    k_fused<<<(Bv*HWv)/PXB, 512, fusedSmem>>>(bias, out);
}